// round 2
// baseline (speedup 1.0000x reference)
#include <cuda_runtime.h>
#include <cuda_bf16.h>
#include <cstddef>

// JPEG 8x8 block DCT + quantization scaling.
// out[b, k*8+l, hb, wb] = DCT2(x-128)[k][l] / (factor(QF_b) * Q[k][l])
// One thread per 8x8 block.
//  - rf = 1/factor and the -128 DC shift are folded into the PASS-1 coefficient
//    registers (7 regs + 1 shift reg per thread).
//  - 100/Q[k][l] is folded into the PASS-2 coefficient immediates at compile time.
//  - streaming stores (__stcs) keep the read-only input resident in L2.

#define C1A 0.49039264020161522f   // 0.5*cos(1*pi/16)
#define C1B 0.46193976625564337f   // 0.5*cos(2*pi/16)
#define C1C 0.41573480615127262f   // 0.5*cos(3*pi/16)
#define C1D 0.35355339059327376f   // 1/(2*sqrt(2))
#define C1E 0.27778511650980114f   // 0.5*cos(5*pi/16)
#define C1F 0.19134171618254489f   // 0.5*cos(6*pi/16)
#define C1G 0.09754516100806417f   // 0.5*cos(7*pi/16)

// Pass 1 (DCT along rows dim), coefficients pre-scaled by rf in registers.
// Writes results back in place. DC shift (rf*128*8*C1D) folded into v0.
#define P1COL(c)                                                              \
    {                                                                          \
        float t0 = x[0][c], t1 = x[1][c], t2 = x[2][c], t3 = x[3][c];          \
        float t4 = x[4][c], t5 = x[5][c], t6 = x[6][c], t7 = x[7][c];          \
        float s0 = t0 + t7, s1 = t1 + t6, s2 = t2 + t5, s3 = t3 + t4;          \
        float d0 = t0 - t7, d1 = t1 - t6, d2 = t2 - t5, d3 = t3 - t4;          \
        float u0 = s0 + s3, u1 = s1 + s2;                                      \
        float w0 = s0 - s3, w1 = s1 - s2;                                      \
        x[0][c] = dd_ * (u0 + u1) - shift_;                                    \
        x[4][c] = dd_ * (u0 - u1);                                             \
        x[2][c] = cb_ * w0 + cf_ * w1;                                         \
        x[6][c] = cf_ * w0 - cb_ * w1;                                         \
        x[1][c] = ca_ * d0 + cc_ * d1 + ce_ * d2 + cg_ * d3;                   \
        x[3][c] = cc_ * d0 - cg_ * d1 - ca_ * d2 - ce_ * d3;                   \
        x[5][c] = ce_ * d0 - ca_ * d1 + cg_ * d2 + cc_ * d3;                   \
        x[7][c] = cg_ * d0 - ce_ * d1 + cc_ * d2 - ca_ * d3;                   \
    }

// Pass 2 (DCT along cols dim) for row k, with invQ[k][l] folded into the
// compile-time coefficient products. Stores directly with streaming hint.
#define P2ROW(k, q0, q1, q2, q3, q4, q5, q6, q7)                               \
    {                                                                          \
        float t0 = x[k][0], t1 = x[k][1], t2 = x[k][2], t3 = x[k][3];          \
        float t4 = x[k][4], t5 = x[k][5], t6 = x[k][6], t7 = x[k][7];          \
        float s0 = t0 + t7, s1 = t1 + t6, s2 = t2 + t5, s3 = t3 + t4;          \
        float d0 = t0 - t7, d1 = t1 - t6, d2 = t2 - t5, d3 = t3 - t4;          \
        float u0 = s0 + s3, u1 = s1 + s2;                                      \
        float w0 = s0 - s3, w1 = s1 - s2;                                      \
        float* dk = dst + ((size_t)((k) * 8) << 14);                           \
        __stcs(dk + (0 << 14), (C1D * (q0)) * (u0 + u1));                      \
        __stcs(dk + (4 << 14), (C1D * (q4)) * (u0 - u1));                      \
        __stcs(dk + (2 << 14), (C1B * (q2)) * w0 + (C1F * (q2)) * w1);         \
        __stcs(dk + (6 << 14), (C1F * (q6)) * w0 - (C1B * (q6)) * w1);         \
        __stcs(dk + (1 << 14), (C1A * (q1)) * d0 + (C1C * (q1)) * d1 +         \
                               (C1E * (q1)) * d2 + (C1G * (q1)) * d3);         \
        __stcs(dk + (3 << 14), (C1C * (q3)) * d0 - (C1G * (q3)) * d1 -         \
                               (C1A * (q3)) * d2 - (C1E * (q3)) * d3);         \
        __stcs(dk + (5 << 14), (C1E * (q5)) * d0 - (C1A * (q5)) * d1 +         \
                               (C1G * (q5)) * d2 + (C1C * (q5)) * d3);         \
        __stcs(dk + (7 << 14), (C1G * (q7)) * d0 - (C1E * (q7)) * d1 +         \
                               (C1C * (q7)) * d2 - (C1A * (q7)) * d3);         \
    }

__global__ void __launch_bounds__(128, 7)
jpeg_dct_kernel(const float* __restrict__ img,
                const float* __restrict__ qf,
                float* __restrict__ out)
{
    int tid = blockIdx.x * blockDim.x + threadIdx.x;
    int wb = tid & 127;          // block col  (fastest -> coalesced)
    int hb = (tid >> 7) & 127;   // block row
    int b  = tid >> 14;          // batch

    const float* src = img + ((size_t)b << 20) + ((size_t)hb << 13) + (wb << 3);

    // Load the 8x8 block (16 front-batched LDG.128 per thread).
    float x[8][8];
#pragma unroll
    for (int r = 0; r < 8; r++) {
        float4 lo = *(const float4*)(src + r * 1024);
        float4 hi = *(const float4*)(src + r * 1024 + 4);
        x[r][0] = lo.x; x[r][1] = lo.y; x[r][2] = lo.z; x[r][3] = lo.w;
        x[r][4] = hi.x; x[r][5] = hi.y; x[r][6] = hi.z; x[r][7] = hi.w;
    }

    float q = __ldg(&qf[b]);
    float factor = (q < 50.0f) ? (5000.0f / q) : (200.0f - 2.0f * q);
    float rf = 1.0f / factor;

    // Pass-1 coefficients pre-scaled by rf; DC shift = rf * 128*8*(1/(2*sqrt2)).
    float ca_ = rf * C1A, cb_ = rf * C1B, cc_ = rf * C1C, dd_ = rf * C1D;
    float ce_ = rf * C1E, cf_ = rf * C1F, cg_ = rf * C1G;
    float shift_ = rf * 362.03867196751236f;

    // Pass 1: DCT along r for each column c (in place).
    P1COL(0) P1COL(1) P1COL(2) P1COL(3)
    P1COL(4) P1COL(5) P1COL(6) P1COL(7)

    // Pass 2: DCT along c for each row k, invQ folded, direct stores.
    float* dst = out + ((size_t)b << 20) + (hb << 7) + wb;

    P2ROW(0, 6.25f, 9.0909090909090910f, 10.0f, 6.25f,
             4.1666666666666667f, 2.5f, 1.9607843137254901f, 1.6393442622950820f)
    P2ROW(1, 8.3333333333333333f, 8.3333333333333333f, 7.1428571428571432f, 5.2631578947368425f,
             3.8461538461538463f, 1.7241379310344827f, 1.6666666666666667f, 1.8181818181818181f)
    P2ROW(2, 7.1428571428571432f, 7.6923076923076925f, 6.25f, 4.1666666666666667f,
             2.5f, 1.7543859649122806f, 1.4492753623188406f, 1.7857142857142858f)
    P2ROW(3, 7.1428571428571432f, 5.8823529411764710f, 4.5454545454545459f, 3.4482758620689657f,
             1.9607843137254901f, 1.1494252873563218f, 1.25f, 1.6129032258064515f)
    P2ROW(4, 5.5555555555555554f, 4.5454545454545459f, 2.7027027027027026f, 1.7857142857142858f,
             1.4705882352941178f, 0.91743119266055051f, 0.97087378640776700f, 1.2987012987012987f)
    P2ROW(5, 4.1666666666666667f, 2.7777777777777777f, 1.8181818181818181f, 1.5625f,
             1.2345679012345678f, 0.96153846153846156f, 0.88495575221238942f, 1.0869565217391304f)
    P2ROW(6, 2.0408163265306123f, 1.5625f, 1.2820512820512820f, 1.1494252873563218f,
             0.97087378640776700f, 0.82644628099173556f, 0.83333333333333337f, 0.99009900990099009f)
    P2ROW(7, 1.3888888888888888f, 1.0869565217391304f, 1.0526315789473684f, 1.0204081632653061f,
             0.89285714285714285f, 1.0f, 0.97087378640776700f, 1.0101010101010102f)
}

extern "C" void kernel_launch(void* const* d_in, const int* in_sizes, int n_in,
                              void* d_out, int out_size)
{
    const float* img = (const float*)d_in[0];
    const float* qf  = (const float*)d_in[1];
    float* out = (float*)d_out;

    int B = in_sizes[0] >> 20;          // elements / (1024*1024)
    int total_threads = B * 128 * 128;  // one thread per 8x8 block
    int block = 128;
    int grid = (total_threads + block - 1) / block;
    jpeg_dct_kernel<<<grid, block>>>(img, qf, out);
}